// round 2
// baseline (speedup 1.0000x reference)
#include <cuda_runtime.h>
#include <math.h>

#define BB   8
#define NN   4096
#define DD   64
#define KNN  20
#define OO   64

// ---------------- scratch (__device__ globals: allocation-free) ----------------
__device__ float g_sq[BB*NN];
__device__ float g_y [BB*NN*OO];
__device__ float g_z [BB*NN*OO];
__device__ int   g_idx[BB*NN*KNN];
__device__ float g_h [BB*NN*OO];
__device__ float g_psum[128*OO];
__device__ float g_psq [128*OO];
__device__ float g_a [OO];
__device__ float g_bb2[OO];

// ---------------- kernel 1: per-point sumsq, y = x·w1^T, z = x·(w2-w1)^T -------
__global__ __launch_bounds__(128) void prep_kernel(const float* __restrict__ x,
                                                   const float* __restrict__ w)
{
    __shared__ float ws[64*128];
    int tid = threadIdx.x;
    #pragma unroll
    for (int i = 0; i < 64; i++) ws[i*128 + tid] = w[i*128 + tid];
    __syncthreads();

    int b = blockIdx.y;
    int n = blockIdx.x * 128 + tid;
    const float* xb = x + b * (DD*NN);

    float p[DD];
    float sq = 0.f;
    #pragma unroll
    for (int d = 0; d < DD; d++) { p[d] = xb[d*NN + n]; sq = fmaf(p[d], p[d], sq); }
    g_sq[b*NN + n] = sq;

    float* yp = g_y + (b*NN + n)*OO;
    float* zp = g_z + (b*NN + n)*OO;
    #pragma unroll 4
    for (int o = 0; o < OO; o++) {
        float ya = 0.f, za = 0.f;
        #pragma unroll
        for (int d = 0; d < DD; d++) {
            float w1 = ws[o*128 + d];
            float w2 = ws[o*128 + 64 + d];
            ya = fmaf(p[d], w1, ya);
            za = fmaf(p[d], w2 - w1, za);
        }
        yp[o] = ya; zp[o] = za;
    }
}

// ---------------- kernel 2: register-tiled Gram + running top-20 ---------------
__device__ __forceinline__ void topk_insert(float (&best)[KNN], int (&bidx)[KNN],
                                            float c, int m)
{
    if (c < best[KNN-1]) {
        best[KNN-1] = c; bidx[KNN-1] = m;
        #pragma unroll
        for (int t = KNN-1; t > 0; --t) {
            if (best[t-1] > best[t]) {
                float tf = best[t-1]; best[t-1] = best[t]; best[t] = tf;
                int   ti = bidx[t-1]; bidx[t-1] = bidx[t]; bidx[t] = ti;
            }
        }
    }
}

__global__ __launch_bounds__(256) void knn_kernel(const float* __restrict__ x)
{
    __shared__ float sXr[64][128];      // 32 KB   A tile (rows), resident
    __shared__ float sXm[2][64][128];   // 64 KB   B tiles, double buffered
    __shared__ float sD [128][129];     // ~64 KB  criterion tile (padded)
    __shared__ float sSq[2][128];

    const int tid = threadIdx.x;
    const int b   = blockIdx.y;
    const int r0  = blockIdx.x * 128;
    const float* xb = x + b * (DD*NN);
    const float* sqb = g_sq + b*NN;

    const int ty = tid >> 4;   // 0..15 : row sub-tile
    const int tx = tid & 15;   // 0..15 : col sub-tile

    // load A tile (64 d x 128 r), coalesced along n
    #pragma unroll
    for (int i = tid; i < 64*32; i += 256) {
        int d  = i >> 5;
        int c4 = (i & 31) * 4;
        *(float4*)&sXr[d][c4] = *(const float4*)&xb[d*NN + r0 + c4];
    }
    // preload m-tile 0
    #pragma unroll
    for (int i = tid; i < 64*32; i += 256) {
        int d  = i >> 5;
        int c4 = (i & 31) * 4;
        *(float4*)&sXm[0][d][c4] = *(const float4*)&xb[d*NN + c4];
    }
    if (tid < 128) sSq[0][tid] = sqb[tid];
    __syncthreads();

    float best[KNN];
    int   bidx[KNN];
    #pragma unroll
    for (int j = 0; j < KNN; j++) { best[j] = 3.4e38f; bidx[j] = 0; }

    for (int t = 0; t < NN/128; t++) {
        const int cur = t & 1;
        const int nxt = cur ^ 1;

        // prefetch next m-tile (buffer nxt is free: last read finished before
        // the final __syncthreads of iteration t-1)
        if (t + 1 < NN/128) {
            int m0n = (t + 1) * 128;
            #pragma unroll
            for (int i = tid; i < 64*32; i += 256) {
                int d  = i >> 5;
                int c4 = (i & 31) * 4;
                *(float4*)&sXm[nxt][d][c4] = *(const float4*)&xb[d*NN + m0n + c4];
            }
            if (tid < 128) sSq[nxt][tid] = sqb[m0n + tid];
        }

        // 8x8 register-tile GEMM: dot(r, m) over d=64
        float c[8][8];
        #pragma unroll
        for (int i = 0; i < 8; i++)
            #pragma unroll
            for (int j = 0; j < 8; j++) c[i][j] = 0.f;

        #pragma unroll 8
        for (int d = 0; d < 64; d++) {
            float4 a0 = *(const float4*)&sXr[d][ty*8];
            float4 a1 = *(const float4*)&sXr[d][ty*8 + 4];
            float4 b0 = *(const float4*)&sXm[cur][d][tx*8];
            float4 b1 = *(const float4*)&sXm[cur][d][tx*8 + 4];
            float av[8] = {a0.x,a0.y,a0.z,a0.w,a1.x,a1.y,a1.z,a1.w};
            float bv[8] = {b0.x,b0.y,b0.z,b0.w,b1.x,b1.y,b1.z,b1.w};
            #pragma unroll
            for (int i = 0; i < 8; i++)
                #pragma unroll
                for (int j = 0; j < 8; j++)
                    c[i][j] = fmaf(av[i], bv[j], c[i][j]);
        }

        // criterion = sq[m] - 2*dot  (monotone in d2 per row)
        #pragma unroll
        for (int i = 0; i < 8; i++) {
            #pragma unroll
            for (int j = 0; j < 8; j++)
                sD[ty*8 + i][tx*8 + j] = sSq[cur][tx*8 + j] - 2.f*c[i][j];
        }
        __syncthreads();

        // scan tile: thread r owns row r's running top-20
        if (tid < 128) {
            const int m0 = t * 128;
            #pragma unroll 4
            for (int m = 0; m < 128; m++)
                topk_insert(best, bidx, sD[tid][m], m0 + m);
        }
        __syncthreads();
    }

    if (tid < 128) {
        int* op = g_idx + (b*NN + r0 + tid)*KNN;
        #pragma unroll
        for (int j = 0; j < KNN; j++) op[j] = bidx[j];
    }
}

// ---------------- kernel 3: gather-max + h + BN partial sums -------------------
__global__ __launch_bounds__(256) void hmax_kernel()
{
    int tid = threadIdx.x;
    int warp = tid >> 5, lane = tid & 31;
    int b = blockIdx.y;
    int nbase = blockIdx.x * 256 + warp * 32;
    const float* yb = g_y + b*NN*OO;

    float s0 = 0.f, s1 = 0.f, q0 = 0.f, q1 = 0.f;
    for (int i = 0; i < 32; i++) {
        int n = nbase + i;
        const int* ip = g_idx + (b*NN + n)*KNN;
        float m0v = -3.4e38f, m1v = -3.4e38f;
        #pragma unroll
        for (int k = 0; k < KNN; k++) {
            int m = ip[k];
            const float* yr = yb + m*OO;
            m0v = fmaxf(m0v, yr[lane]);
            m1v = fmaxf(m1v, yr[lane + 32]);
        }
        const float* zr = g_z + (b*NN + n)*OO;
        float h0 = zr[lane]      + m0v;
        float h1 = zr[lane + 32] + m1v;
        g_h[(b*NN + n)*OO + lane]      = h0;
        g_h[(b*NN + n)*OO + lane + 32] = h1;
        s0 += h0; s1 += h1;
        q0 = fmaf(h0, h0, q0); q1 = fmaf(h1, h1, q1);
    }

    __shared__ float ps[8][64], pq[8][64];
    ps[warp][lane]      = s0; ps[warp][lane + 32] = s1;
    pq[warp][lane]      = q0; pq[warp][lane + 32] = q1;
    __syncthreads();
    if (tid < 64) {
        float S = 0.f, Q = 0.f;
        #pragma unroll
        for (int wr = 0; wr < 8; wr++) { S += ps[wr][tid]; Q += pq[wr][tid]; }
        int blk = b*16 + blockIdx.x;
        g_psum[blk*64 + tid] = S;
        g_psq [blk*64 + tid] = Q;
    }
}

// ---------------- kernel 4: deterministic fp64 stats reduce (parallel) ---------
__global__ __launch_bounds__(256) void stats_kernel(const float* __restrict__ gamma,
                                                    const float* __restrict__ beta)
{
    __shared__ double sS[256], sQ[256];
    int ch = threadIdx.x & 63;
    int sl = threadIdx.x >> 6;        // 4 slices per channel
    double S = 0.0, Q = 0.0;
    for (int i = sl; i < 128; i += 4) {
        S += (double)g_psum[i*64 + ch];
        Q += (double)g_psq [i*64 + ch];
    }
    sS[threadIdx.x] = S; sQ[threadIdx.x] = Q;
    __syncthreads();
    if (sl == 0) {
        // fixed order: slice 0 + 1 + 2 + 3 (deterministic)
        double St = sS[ch] + sS[64+ch] + sS[128+ch] + sS[192+ch];
        double Qt = sQ[ch] + sQ[64+ch] + sQ[128+ch] + sQ[192+ch];
        double cnt  = (double)(BB * NN);
        double mean = St / cnt;
        double var  = Qt / cnt - mean * mean;
        float inv = (float)(1.0 / sqrt(var + 1e-5));
        float a = gamma[ch] * inv;
        g_a  [ch] = a;
        g_bb2[ch] = beta[ch] - (float)mean * a;
    }
}

// ---------------- kernel 5: BN affine + exact GELU + transpose -----------------
__global__ __launch_bounds__(256) void final_kernel(float* __restrict__ out)
{
    __shared__ float t[64][65];
    int tid = threadIdx.x;
    int b = blockIdx.y;
    int n0 = blockIdx.x * 64;
    const float* hb = g_h + b*NN*OO;

    #pragma unroll
    for (int it = 0; it < 16; it++) {
        int idx = it*256 + tid;
        int nl = idx >> 6, o = idx & 63;
        t[nl][o] = hb[(n0 + nl)*OO + o];
    }
    __syncthreads();

    float* ob = out + b*OO*NN;
    #pragma unroll
    for (int it = 0; it < 16; it++) {
        int idx = it*256 + tid;
        int o = idx >> 6, nl = idx & 63;
        float v = t[nl][o] * g_a[o] + g_bb2[o];
        ob[o*NN + n0 + nl] = 0.5f * v * (1.f + erff(v * 0.70710678118654752f));
    }
}

// ---------------- launch --------------------------------------------------------
extern "C" void kernel_launch(void* const* d_in, const int* in_sizes, int n_in,
                              void* d_out, int out_size)
{
    const float* x     = (const float*)d_in[0];
    const float* w     = (const float*)d_in[1];
    const float* gamma = (const float*)d_in[2];
    const float* beta  = (const float*)d_in[3];
    float* out = (float*)d_out;

    prep_kernel <<<dim3(NN/128, BB), 128>>>(x, w);
    knn_kernel  <<<dim3(NN/128, BB), 256>>>(x);
    hmax_kernel <<<dim3(NN/256, BB), 256>>>();
    stats_kernel<<<1, 256>>>(gamma, beta);
    final_kernel<<<dim3(NN/64, BB), 256>>>(out);
}

// round 4
// speedup vs baseline: 1.2509x; 1.2509x over previous
#include <cuda_runtime.h>
#include <cuda_bf16.h>
#include <stdint.h>
#include <math.h>

#define BB   8
#define NN   4096
#define DD   64
#define KNN  20
#define OO   64

// ---------------- scratch (__device__ globals: allocation-free) ----------------
__device__ float g_sq[BB*NN];
__device__ float g_y [BB*NN*OO];
__device__ float g_z [BB*NN*OO];
__device__ int   g_idx[BB*NN*KNN];
__device__ float g_h [BB*NN*OO];
__device__ float g_psum[128*OO];
__device__ float g_psq [128*OO];
__device__ float g_a [OO];
__device__ float g_bb2[OO];
// bf16x3 split layouts, k-major per point, K=192:
//   A' = [hi | lo | hi]   B' = [hi | hi | lo]   (dot(A',B') = hh + lh + hl)
__device__ __nv_bfloat16 g_xa[(size_t)BB*NN*192];
__device__ __nv_bfloat16 g_xb[(size_t)BB*NN*192];

__device__ __forceinline__ uint32_t smem_u32(const void* p) {
    uint32_t a;
    asm("{ .reg .u64 t; cvta.to.shared.u64 t, %1; cvt.u32.u64 %0, t; }" : "=r"(a) : "l"(p));
    return a;
}
__device__ __forceinline__ uint32_t pack_bf2(__nv_bfloat16 a, __nv_bfloat16 b) {
    return (uint32_t)__bfloat16_as_ushort(a) | ((uint32_t)__bfloat16_as_ushort(b) << 16);
}

// ---------------- kernel 1: sumsq, y, z, and bf16x3 split layouts --------------
__global__ __launch_bounds__(128) void prep_kernel(const float* __restrict__ x,
                                                   const float* __restrict__ w)
{
    __shared__ float ws[64*128];
    int tid = threadIdx.x;
    #pragma unroll
    for (int i = 0; i < 64; i++) ws[i*128 + tid] = w[i*128 + tid];
    __syncthreads();

    int b = blockIdx.y;
    int n = blockIdx.x * 128 + tid;
    const float* xb = x + b * (DD*NN);

    float p[DD];
    float sq = 0.f;
    #pragma unroll
    for (int d = 0; d < DD; d++) { p[d] = xb[d*NN + n]; sq = fmaf(p[d], p[d], sq); }
    g_sq[b*NN + n] = sq;

    // bf16x3 split, vectorized 16B stores. 64 bf16 = 8 uint4 per 64-elem section.
    uint4* pa = (uint4*)(g_xa + (size_t)(b*NN + n)*192);
    uint4* pb = (uint4*)(g_xb + (size_t)(b*NN + n)*192);
    #pragma unroll
    for (int d = 0; d < DD; d += 8) {
        uint32_t hv[4], lv[4];
        #pragma unroll
        for (int j = 0; j < 4; j++) {
            float v0 = p[d + 2*j], v1 = p[d + 2*j + 1];
            __nv_bfloat16 h0 = __float2bfloat16(v0);
            __nv_bfloat16 h1 = __float2bfloat16(v1);
            __nv_bfloat16 l0 = __float2bfloat16(v0 - __bfloat162float(h0));
            __nv_bfloat16 l1 = __float2bfloat16(v1 - __bfloat162float(h1));
            hv[j] = pack_bf2(h0, h1);
            lv[j] = pack_bf2(l0, l1);
        }
        uint4 H = make_uint4(hv[0], hv[1], hv[2], hv[3]);
        uint4 L = make_uint4(lv[0], lv[1], lv[2], lv[3]);
        int c = d >> 3;
        pa[c] = H; pa[8 + c] = L; pa[16 + c] = H;
        pb[c] = H; pb[8 + c] = H; pb[16 + c] = L;
    }

    float* yp = g_y + (b*NN + n)*OO;
    float* zp = g_z + (b*NN + n)*OO;
    #pragma unroll 2
    for (int o = 0; o < OO; o += 4) {
        float ya[4], za[4];
        #pragma unroll
        for (int j = 0; j < 4; j++) { ya[j] = 0.f; za[j] = 0.f; }
        #pragma unroll
        for (int d = 0; d < DD; d++) {
            float pd = p[d];
            #pragma unroll
            for (int j = 0; j < 4; j++) {
                float w1 = ws[(o+j)*128 + d];
                float w2 = ws[(o+j)*128 + 64 + d];
                ya[j] = fmaf(pd, w1, ya[j]);
                za[j] = fmaf(pd, w2 - w1, za[j]);
            }
        }
        *(float4*)&yp[o] = make_float4(ya[0], ya[1], ya[2], ya[3]);
        *(float4*)&zp[o] = make_float4(za[0], za[1], za[2], za[3]);
    }
}

// ---------------- kernel 2: HMMA (mma.sync bf16x3) Gram + top-20 ---------------
__device__ __forceinline__ void topk_insert(float (&best)[KNN], int (&bidx)[KNN],
                                            float c, int m)
{
    if (c < best[KNN-1]) {
        best[KNN-1] = c; bidx[KNN-1] = m;
        #pragma unroll
        for (int t = KNN-1; t > 0; --t) {
            if (best[t-1] > best[t]) {
                float tf = best[t-1]; best[t-1] = best[t]; best[t] = tf;
                int   ti = bidx[t-1]; bidx[t-1] = bidx[t]; bidx[t] = ti;
            }
        }
    }
}

// smem layout: rows stride 200 bf16 = 400B (mod-32-words = 4 -> conflict-free ldmatrix)
#define SM_A   0
#define SM_B   51200
#define SM_D   102400            // float sD[128][130]
#define SM_SQ  168960            // float sqs[128]
#define SM_TOT 169472

__global__ __launch_bounds__(256) void knn_kernel()
{
    extern __shared__ char smem[];
    const uint32_t sb = smem_u32(smem);
    float* sD  = (float*)(smem + SM_D);
    float* sqs = (float*)(smem + SM_SQ);

    const int tid  = threadIdx.x;
    const int lane = tid & 31;
    const int w    = tid >> 5;
    const int b    = blockIdx.y;
    const int r0   = blockIdx.x * 128;

    // copy A' rows r0..r0+127 (384B/row) into smem (400B/row)
    {
        const char* ga = (const char*)(g_xa + (size_t)(b*NN + r0)*192);
        #pragma unroll 4
        for (int i = tid; i < 128*24; i += 256) {
            int p = i / 24, c = i % 24;
            *(uint4*)(smem + SM_A + p*400 + c*16) = *(const uint4*)(ga + p*384 + c*16);
        }
    }

    float best[KNN];
    int   bidx[KNN];
    #pragma unroll
    for (int j = 0; j < KNN; j++) { best[j] = 3.4e38f; bidx[j] = 0; }

    const int half  = tid >> 7;          // 0 or 1
    const int srow  = tid & 127;
    const int cbase = half * 64;

    // ldmatrix lane addressing: mm = matrix index (l>>3), rr = l&7
    const int mm = lane >> 3, rr = lane & 7;
    // A: mm bit0 -> row+8, bit1 -> k+8
    const uint32_t aaddr0 = sb + SM_A
        + (uint32_t)((w*16 + ((mm & 1) << 3) + rr) * 400)
        + (uint32_t)(((mm & 2) ? 8 : 0) * 2);
    // B: mm bit1 -> col(point)+8, bit0 -> k+8
    const uint32_t baddr_row = (uint32_t)((((mm & 2) ? 8 : 0) + rr) * 400)
                             + (uint32_t)(((mm & 1) ? 8 : 0) * 2);

    for (int t = 0; t < 32; t++) {
        const int m0 = t * 128;
        // copy B' tile + sq
        {
            const char* gb = (const char*)(g_xb + (size_t)(b*NN + m0)*192);
            #pragma unroll 4
            for (int i = tid; i < 128*24; i += 256) {
                int p = i / 24, c = i % 24;
                *(uint4*)(smem + SM_B + p*400 + c*16) = *(const uint4*)(gb + p*384 + c*16);
            }
            if (tid < 128) sqs[tid] = g_sq[b*NN + m0 + tid];
        }
        __syncthreads();

        // MMA: 16 rows (this warp) x 128 cols, K = 192
        float acc[16][4];
        #pragma unroll
        for (int i = 0; i < 16; i++)
            #pragma unroll
            for (int j = 0; j < 4; j++) acc[i][j] = 0.f;

        #pragma unroll 2
        for (int ks = 0; ks < 12; ks++) {
            uint32_t a0, a1, a2, a3;
            asm volatile("ldmatrix.sync.aligned.m8n8.x4.shared.b16 {%0,%1,%2,%3}, [%4];"
                : "=r"(a0), "=r"(a1), "=r"(a2), "=r"(a3)
                : "r"(aaddr0 + (uint32_t)(ks*32)));
            const uint32_t bb = sb + SM_B + baddr_row + (uint32_t)(ks*32);
            #pragma unroll
            for (int ct = 0; ct < 8; ct++) {
                uint32_t b0, b1, b2, b3;
                asm volatile("ldmatrix.sync.aligned.m8n8.x4.shared.b16 {%0,%1,%2,%3}, [%4];"
                    : "=r"(b0), "=r"(b1), "=r"(b2), "=r"(b3)
                    : "r"(bb + (uint32_t)(ct*16*400)));
                asm volatile("mma.sync.aligned.m16n8k16.row.col.f32.bf16.bf16.f32 "
                    "{%0,%1,%2,%3},{%4,%5,%6,%7},{%8,%9},{%0,%1,%2,%3};"
                    : "+f"(acc[2*ct][0]), "+f"(acc[2*ct][1]),
                      "+f"(acc[2*ct][2]), "+f"(acc[2*ct][3])
                    : "r"(a0), "r"(a1), "r"(a2), "r"(a3), "r"(b0), "r"(b1));
                asm volatile("mma.sync.aligned.m16n8k16.row.col.f32.bf16.bf16.f32 "
                    "{%0,%1,%2,%3},{%4,%5,%6,%7},{%8,%9},{%0,%1,%2,%3};"
                    : "+f"(acc[2*ct+1][0]), "+f"(acc[2*ct+1][1]),
                      "+f"(acc[2*ct+1][2]), "+f"(acc[2*ct+1][3])
                    : "r"(a0), "r"(a1), "r"(a2), "r"(a3), "r"(b2), "r"(b3));
            }
        }

        // stage criterion = sq[m] - 2*dot
        {
            const int rw = w*16 + (lane >> 2);
            const int cb = (lane & 3) * 2;
            #pragma unroll
            for (int i = 0; i < 16; i++) {
                int col = i*8 + cb;
                float s0 = sqs[col], s1 = sqs[col+1];
                *(float2*)&sD[rw*130 + col] =
                    make_float2(fmaf(-2.f, acc[i][0], s0), fmaf(-2.f, acc[i][1], s1));
                *(float2*)&sD[(rw+8)*130 + col] =
                    make_float2(fmaf(-2.f, acc[i][2], s0), fmaf(-2.f, acc[i][3], s1));
            }
        }
        __syncthreads();

        // scan: thread owns half a row, running top-20 over its half of cols
        {
            const float* row = &sD[srow*130 + cbase];
            const int mb = m0 + cbase;
            #pragma unroll 4
            for (int c = 0; c < 64; c++)
                topk_insert(best, bidx, row[c], mb + c);
        }
        __syncthreads();
    }

    // merge the two per-row half-lists (each sorted ascending)
    float* mbf = (float*)(smem + SM_D);
    int*   mbi = (int*)  (smem + SM_D + 256*KNN*4);
    #pragma unroll
    for (int j = 0; j < KNN; j++) { mbf[tid*KNN + j] = best[j]; mbi[tid*KNN + j] = bidx[j]; }
    __syncthreads();
    if (tid < 128) {
        const int ia = tid*KNN, ib = (tid + 128)*KNN;
        int na = 0, nb = 0;
        int* op = g_idx + (b*NN + r0 + tid)*KNN;
        #pragma unroll
        for (int j = 0; j < KNN; j++) {
            float va = mbf[ia + na], vb = mbf[ib + nb];
            if (va <= vb) { op[j] = mbi[ia + na]; na++; }
            else          { op[j] = mbi[ib + nb]; nb++; }
        }
    }
}

// ---------------- kernel 3: gather-max + h + BN partial sums -------------------
__global__ __launch_bounds__(256) void hmax_kernel()
{
    int tid = threadIdx.x;
    int warp = tid >> 5, lane = tid & 31;
    int b = blockIdx.y;
    int nbase = blockIdx.x * 256 + warp * 32;
    const float* yb = g_y + b*NN*OO;

    float s0 = 0.f, s1 = 0.f, q0 = 0.f, q1 = 0.f;
    for (int i = 0; i < 32; i++) {
        int n = nbase + i;
        const int* ip = g_idx + (b*NN + n)*KNN;
        float m0v = -3.4e38f, m1v = -3.4e38f;
        #pragma unroll
        for (int k = 0; k < KNN; k++) {
            int m = ip[k];
            const float* yr = yb + m*OO;
            m0v = fmaxf(m0v, yr[lane]);
            m1v = fmaxf(m1v, yr[lane + 32]);
        }
        const float* zr = g_z + (b*NN + n)*OO;
        float h0 = zr[lane]      + m0v;
        float h1 = zr[lane + 32] + m1v;
        g_h[(b*NN + n)*OO + lane]      = h0;
        g_h[(b*NN + n)*OO + lane + 32] = h1;
        s0 += h0; s1 += h1;
        q0 = fmaf(h0, h0, q0); q1 = fmaf(h1, h1, q1);
    }

    __shared__ float ps[8][64], pq[8][64];
    ps[warp][lane]      = s0; ps[warp][lane + 32] = s1;
    pq[warp][lane]      = q0; pq[warp][lane + 32] = q1;
    __syncthreads();
    if (tid < 64) {
        float S = 0.f, Q = 0.f;
        #pragma unroll
        for (int wr = 0; wr < 8; wr++) { S += ps[wr][tid]; Q += pq[wr][tid]; }
        int blk = b*16 + blockIdx.x;
        g_psum[blk*64 + tid] = S;
        g_psq [blk*64 + tid] = Q;
    }
}

// ---------------- kernel 4: deterministic fp64 stats reduce --------------------
__global__ __launch_bounds__(1024) void stats_kernel(const float* __restrict__ gamma,
                                                     const float* __restrict__ beta)
{
    __shared__ double sS[1024], sQ[1024];
    int ch = threadIdx.x & 63;
    int sl = threadIdx.x >> 6;        // 16 slices per channel
    double S = 0.0, Q = 0.0;
    #pragma unroll
    for (int i = sl; i < 128; i += 16) {
        S += (double)g_psum[i*64 + ch];
        Q += (double)g_psq [i*64 + ch];
    }
    sS[threadIdx.x] = S; sQ[threadIdx.x] = Q;
    __syncthreads();
    if (sl == 0) {
        double St = 0.0, Qt = 0.0;
        #pragma unroll
        for (int k = 0; k < 16; k++) { St += sS[k*64 + ch]; Qt += sQ[k*64 + ch]; }
        double cnt  = (double)(BB * NN);
        double mean = St / cnt;
        double var  = Qt / cnt - mean * mean;
        float inv = (float)(1.0 / sqrt(var + 1e-5));
        float a = gamma[ch] * inv;
        g_a  [ch] = a;
        g_bb2[ch] = beta[ch] - (float)mean * a;
    }
}

// ---------------- kernel 5: BN affine + exact GELU + transpose -----------------
__global__ __launch_bounds__(256) void final_kernel(float* __restrict__ out)
{
    __shared__ float t[64][65];
    int tid = threadIdx.x;
    int b = blockIdx.y;
    int n0 = blockIdx.x * 64;
    const float* hb = g_h + b*NN*OO;

    #pragma unroll
    for (int it = 0; it < 16; it++) {
        int idx = it*256 + tid;
        int nl = idx >> 6, o = idx & 63;
        t[nl][o] = hb[(n0 + nl)*OO + o];
    }
    __syncthreads();

    float* ob = out + b*OO*NN;
    #pragma unroll
    for (int it = 0; it < 16; it++) {
        int idx = it*256 + tid;
        int o = idx >> 6, nl = idx & 63;
        float v = t[nl][o] * g_a[o] + g_bb2[o];
        ob[o*NN + n0 + nl] = 0.5f * v * (1.f + erff(v * 0.70710678118654752f));
    }
}

// ---------------- launch --------------------------------------------------------
extern "C" void kernel_launch(void* const* d_in, const int* in_sizes, int n_in,
                              void* d_out, int out_size)
{
    const float* x     = (const float*)d_in[0];
    const float* w     = (const float*)d_in[1];
    const float* gamma = (const float*)d_in[2];
    const float* beta  = (const float*)d_in[3];
    float* out = (float*)d_out;

    cudaFuncSetAttribute(knn_kernel, cudaFuncAttributeMaxDynamicSharedMemorySize, SM_TOT);

    prep_kernel <<<dim3(NN/128, BB), 128>>>(x, w);
    knn_kernel  <<<dim3(NN/128, BB), 256, SM_TOT>>>();
    hmax_kernel <<<dim3(NN/256, BB), 256>>>();
    stats_kernel<<<1, 1024>>>(gamma, beta);
    final_kernel<<<dim3(NN/64, BB), 256>>>(out);
}